// round 14
// baseline (speedup 1.0000x reference)
#include <cuda_runtime.h>
#include <math.h>

// Problem constants (fixed by reference: B=4, S=2048, D_MODEL=1024, H=16, DK=64)
#define BATCH    4
#define SEQ      2048
#define DMODEL   1024
#define NHEADS   16
#define DK       64
#define BHTOT    (BATCH * NHEADS)
#define MROWS    (BATCH * SEQ)          // 8192

typedef unsigned long long u64;
typedef unsigned int u32;

// ---------------------------------------------------------------------------
// Packed fp32x2 helpers (Blackwell: SASS FFMA2 — 2x fp32 FMA/instr, bit-exact)
// ---------------------------------------------------------------------------
__device__ __forceinline__ u64 dup_f2(float x) {
    u64 r; asm("mov.b64 %0, {%1, %1};" : "=l"(r) : "f"(x)); return r;
}
__device__ __forceinline__ void fma_f2(u64& d, u64 a, u64 b) {
    asm("fma.rn.f32x2 %0, %1, %2, %0;" : "+l"(d) : "l"(a), "l"(b));
}
__device__ __forceinline__ void mul_f2(u64& d, u64 a, u64 b) {
    asm("mul.rn.f32x2 %0, %1, %2;" : "=l"(d) : "l"(a), "l"(b));
}
__device__ __forceinline__ float2 unp_f2(u64 v) {
    float lo, hi; asm("mov.b64 {%0, %1}, %2;" : "=f"(lo), "=f"(hi) : "l"(v));
    return make_float2(lo, hi);
}

// cp.async helpers (16B, L1-bypass)
__device__ __forceinline__ void cp16(u32 dst, const void* src) {
    asm volatile("cp.async.cg.shared.global [%0], [%1], 16;" :: "r"(dst), "l"(src));
}
__device__ __forceinline__ void cp_commit() {
    asm volatile("cp.async.commit_group;");
}
__device__ __forceinline__ void cp_wait_all() {
    asm volatile("cp.async.wait_group 0;");
}

// ---------------------------------------------------------------------------
// Scratch (static device globals — no runtime allocation)
// ---------------------------------------------------------------------------
__device__ float g_q[BHTOT * DK * SEQ];      // [bh][d][s]  (TRANSPOSED, pre-scaled)
__device__ float g_k[BHTOT * DK * SEQ];      // [bh][d][s]  (TRANSPOSED)
__device__ float g_v[BHTOT * SEQ * DK];      // [bh][s][d]
__device__ float g_ctx[MROWS * DMODEL];      // [b*S+s][h*DK+d]

// ---------------------------------------------------------------------------
// GEMM: C[m,n] = (sum_k A[m,k] * W[n,k] + bias[n]) * oscale
// mode 0: C[m][n] row-major     mode 1: [bh][s][d]     mode 2: [bh][d][s] (T)
// Tile 128x128x16, 256 threads, 8x8 micro-tile, FFMA2 accumulators.
// (unchanged — measured at the FFMA2 ceiling)
// ---------------------------------------------------------------------------
#define GBM 128
#define GBN 128
#define GBK 16
#define GSTR 132

__global__ __launch_bounds__(256) void gemm_nt_bias(
    const float* __restrict__ A, const float* __restrict__ W,
    const float* __restrict__ bias, float* __restrict__ C,
    int K, int N, int mode, float oscale)
{
    __shared__ float As[GBK * GSTR];
    __shared__ float Bs[GBK * GSTR];

    const int tid = threadIdx.x;
    const int tx = tid & 15;
    const int ty = tid >> 4;
    const int mBase = blockIdx.y * GBM;
    const int nBase = blockIdx.x * GBN;

    const float* Aptr = A + (size_t)mBase * K;
    const float* Wptr = W + (size_t)nBase * K;

    u64 acc[8][4];
#pragma unroll
    for (int i = 0; i < 8; i++)
#pragma unroll
        for (int j = 0; j < 4; j++) acc[i][j] = 0ull;

    for (int k0 = 0; k0 < K; k0 += GBK) {
#pragma unroll
        for (int i = 0; i < 2; i++) {
            int v   = tid * 2 + i;
            int row = v >> 2;
            int kc  = (v & 3) * 4;
            float4 a = *(const float4*)(Aptr + (size_t)row * K + k0 + kc);
            float4 b = *(const float4*)(Wptr + (size_t)row * K + k0 + kc);
            As[(kc + 0) * GSTR + row] = a.x;
            As[(kc + 1) * GSTR + row] = a.y;
            As[(kc + 2) * GSTR + row] = a.z;
            As[(kc + 3) * GSTR + row] = a.w;
            Bs[(kc + 0) * GSTR + row] = b.x;
            Bs[(kc + 1) * GSTR + row] = b.y;
            Bs[(kc + 2) * GSTR + row] = b.z;
            Bs[(kc + 3) * GSTR + row] = b.w;
        }
        __syncthreads();

#pragma unroll
        for (int k = 0; k < GBK; k++) {
            float4 a0 = *(const float4*)&As[k * GSTR + ty * 8];
            float4 a1 = *(const float4*)&As[k * GSTR + ty * 8 + 4];
            ulonglong2 b0 = *(const ulonglong2*)&Bs[k * GSTR + tx * 8];
            ulonglong2 b1 = *(const ulonglong2*)&Bs[k * GSTR + tx * 8 + 4];
            u64 bb0 = b0.x, bb1 = b0.y, bb2 = b1.x, bb3 = b1.y;
            float av[8] = {a0.x, a0.y, a0.z, a0.w, a1.x, a1.y, a1.z, a1.w};
#pragma unroll
            for (int i = 0; i < 8; i++) {
                u64 ad = dup_f2(av[i]);
                fma_f2(acc[i][0], ad, bb0);
                fma_f2(acc[i][1], ad, bb1);
                fma_f2(acc[i][2], ad, bb2);
                fma_f2(acc[i][3], ad, bb3);
            }
        }
        __syncthreads();
    }

#pragma unroll
    for (int i = 0; i < 8; i++) {
        int m = mBase + ty * 8 + i;
        int b = m >> 11;              // m / SEQ
        int s = m & (SEQ - 1);
#pragma unroll
        for (int jp = 0; jp < 4; jp++) {
            int n = nBase + tx * 8 + jp * 2;
            float2 v = unp_f2(acc[i][jp]);
            v.x = (v.x + bias[n])     * oscale;
            v.y = (v.y + bias[n + 1]) * oscale;
            if (mode == 0) {
                *(float2*)&C[(size_t)m * N + n] = v;
            } else if (mode == 1) {
                int h = n >> 6, d = n & (DK - 1);
                *(float2*)&C[(((size_t)(b * NHEADS + h)) * SEQ + s) * DK + d] = v;
            } else {
                int h = n >> 6, d = n & (DK - 1);
                size_t base = (((size_t)(b * NHEADS + h)) * DK + d) * SEQ + s;
                C[base]       = v.x;
                C[base + SEQ] = v.y;   // d+1, same head (pairs stay inside a head)
            }
        }
    }
}

// ---------------------------------------------------------------------------
// Flash attention v4: 128-row Q tiles, 128-col KV tiles, online softmax.
// 256 threads as 16(tx) x 16(ty); S micro-tile 8m x 8n per thread
// -> 0.5 B/FLOP in the S loop (was 0.75): lifts the 128B/cyc crossbar cap
// off the FFMA2 pipe (R12 was pinned at fma=66.5% == crossbar ratio).
// Q/K arrive transposed ([bh][d][s], Q pre-scaled); all fills are straight
// cp.async copies. V ping-pong; K prefetched into its single buffer after
// the S-loop's last read, overlapping P-store + P@V.
// smem: Qst[64][128] 32KB, Kst[64][128] 32KB, V 2x[128][64] 64KB,
// Ps[128][128] 64KB = 192KB -> 1 CTA/SM (8 warps; 32-deep per-thread ILP).
// ---------------------------------------------------------------------------
#define FBM 128
#define FBN 128
#define NTILE (SEQ / FBN)
#define FLASH_SMEM ((DK * FBM + DK * FBN + 2 * FBN * DK + FBM * FBN) * (int)sizeof(float))

extern __shared__ float fsm[];

__global__ __launch_bounds__(256) void flash_attn_kernel(
    const float* __restrict__ Q, const float* __restrict__ K,
    const float* __restrict__ V, float* __restrict__ Octx)
{
    float* Qst = fsm;                       // [64][128]  Qst[d*128 + m]
    float* Kst = Qst + DK * FBM;            // [64][128]  Kst[d*128 + n]
    float* Vs0 = Kst + DK * FBN;            // [128][64]  ping
    float* Vs1 = Vs0 + FBN * DK;            // [128][64]  pong
    float* Ps  = Vs1 + FBN * DK;            // [128][128] Ps[m*128 + n]

    const int tid = threadIdx.x;
    const int tx = tid & 15;
    const int ty = tid >> 4;
    const int bh = blockIdx.y;
    const int mBase = blockIdx.x * FBM;

    const float* Qt = Q + (size_t)bh * DK * SEQ;   // [d][s]
    const float* Kt = K + (size_t)bh * DK * SEQ;   // [d][s]
    const float* Vp = V + (size_t)bh * SEQ * DK;   // [s][d]

    const u32 sQ  = (u32)__cvta_generic_to_shared(Qst);
    const u32 sK  = (u32)__cvta_generic_to_shared(Kst);
    const u32 sV0 = (u32)__cvta_generic_to_shared(Vs0);
    const u32 sV1 = (u32)__cvta_generic_to_shared(Vs1);

    // Preload Q tile, K tile 0, V tile 0 — all straight async copies.
#pragma unroll
    for (int k = 0; k < 8; k++) {              // Q: 2048 16B chunks
        int c = tid + k * 256;
        int d = c >> 5, m4 = (c & 31) * 4;
        cp16(sQ + (u32)(d * FBM + m4) * 4, Qt + (size_t)d * SEQ + mBase + m4);
    }
#pragma unroll
    for (int k = 0; k < 8; k++) {              // K: 2048 16B chunks
        int c = tid + k * 256;
        int d = c >> 5, n4 = (c & 31) * 4;
        cp16(sK + (u32)(d * FBN + n4) * 4, Kt + (size_t)d * SEQ + n4);
    }
#pragma unroll
    for (int k = 0; k < 8; k++) {              // V: 2048 16B chunks
        int c = tid + k * 256;
        cp16(sV0 + (u32)c * 16, Vp + c * 4);
    }
    cp_commit();
    cp_wait_all();
    __syncthreads();

    u64 acc[8][2];                 // O accum: 8 rows x 2 d-pairs
    float mi[8], li[8];
#pragma unroll
    for (int i = 0; i < 8; i++) {
        mi[i] = -1e30f; li[i] = 0.0f;
        acc[i][0] = 0ull; acc[i][1] = 0ull;
    }

    for (int it = 0; it < NTILE; it++) {
        const int n0 = it * FBN;
        const float* Vcur = (it & 1) ? Vs1 : Vs0;
        const u32 sVnxt   = (it & 1) ? sV0 : sV1;

        // Prefetch next V tile (overlaps the whole tile's compute)
        if (it + 1 < NTILE) {
#pragma unroll
            for (int k = 0; k < 8; k++) {
                int c = tid + k * 256;
                cp16(sVnxt + (u32)c * 16, Vp + (size_t)(n0 + FBN) * DK + c * 4);
            }
            cp_commit();
        }

        // ---- S = Q K^T (scale pre-folded into Q); 8x8 micro-tile ----
        u64 sp[8][4];
#pragma unroll
        for (int i = 0; i < 8; i++) {
            sp[i][0] = 0ull; sp[i][1] = 0ull; sp[i][2] = 0ull; sp[i][3] = 0ull;
        }

#pragma unroll 2
        for (int d = 0; d < DK; d++) {
            ulonglong2 b0 = *(const ulonglong2*)&Kst[d * FBN + tx * 8];
            ulonglong2 b1 = *(const ulonglong2*)&Kst[d * FBN + tx * 8 + 4];
            float4 a0 = *(const float4*)&Qst[d * FBM + ty * 8];
            float4 a1 = *(const float4*)&Qst[d * FBM + ty * 8 + 4];
            float av[8] = {a0.x, a0.y, a0.z, a0.w, a1.x, a1.y, a1.z, a1.w};
#pragma unroll
            for (int i = 0; i < 8; i++) {
                u64 ad = dup_f2(av[i]);
                fma_f2(sp[i][0], ad, b0.x);
                fma_f2(sp[i][1], ad, b0.y);
                fma_f2(sp[i][2], ad, b1.x);
                fma_f2(sp[i][3], ad, b1.y);
            }
        }

        // ---- Online softmax per row (max across 16 tx lanes; sum deferred)
        // and P store (Ps is dedicated: store needs no barrier) ----
#pragma unroll
        for (int i = 0; i < 8; i++) {
            float2 p0 = unp_f2(sp[i][0]);
            float2 p1 = unp_f2(sp[i][1]);
            float2 p2 = unp_f2(sp[i][2]);
            float2 p3 = unp_f2(sp[i][3]);
            float s0 = p0.x, s1 = p0.y, s2 = p1.x, s3 = p1.y;
            float s4 = p2.x, s5 = p2.y, s6 = p3.x, s7 = p3.y;

            float rm = fmaxf(fmaxf(fmaxf(s0, s1), fmaxf(s2, s3)),
                             fmaxf(fmaxf(s4, s5), fmaxf(s6, s7)));
#pragma unroll
            for (int off = 8; off > 0; off >>= 1)
                rm = fmaxf(rm, __shfl_xor_sync(0xffffffffu, rm, off));
            float mnew = fmaxf(mi[i], rm);
            float alpha = __expf(mi[i] - mnew);
            s0 = __expf(s0 - mnew); s1 = __expf(s1 - mnew);
            s2 = __expf(s2 - mnew); s3 = __expf(s3 - mnew);
            s4 = __expf(s4 - mnew); s5 = __expf(s5 - mnew);
            s6 = __expf(s6 - mnew); s7 = __expf(s7 - mnew);
            float rs = ((s0 + s1) + (s2 + s3)) + ((s4 + s5) + (s6 + s7));
            li[i] = li[i] * alpha + rs;
            mi[i] = mnew;
            u64 al = dup_f2(alpha);
            mul_f2(acc[i][0], acc[i][0], al);
            mul_f2(acc[i][1], acc[i][1], al);

            float* prow = &Ps[(ty * 8 + i) * FBN + tx * 8];
            *(float4*)(prow)     = make_float4(s0, s1, s2, s3);
            *(float4*)(prow + 4) = make_float4(s4, s5, s6, s7);
        }

        __syncthreads();   // all warps done reading Kst + P visible

        // Prefetch next K tile into Kst — overlaps the P@V loop below
        if (it + 1 < NTILE) {
#pragma unroll
            for (int k = 0; k < 8; k++) {
                int c = tid + k * 256;
                int d = c >> 5, n4 = (c & 31) * 4;
                cp16(sK + (u32)(d * FBN + n4) * 4,
                     Kt + (size_t)d * SEQ + (n0 + FBN) + n4);
            }
            cp_commit();
        }

        // ---- O += P @ V — n in chunks of 4; P rows as LDS.128 broadcast ----
#pragma unroll 4
        for (int n = 0; n < FBN; n += 4) {
            float4 p4[8];
#pragma unroll
            for (int i = 0; i < 8; i++)
                p4[i] = *(const float4*)&Ps[(ty * 8 + i) * FBN + n];
#pragma unroll
            for (int nn = 0; nn < 4; nn++) {
                ulonglong2 v2 = *(const ulonglong2*)&Vcur[(n + nn) * DK + tx * 4];
#pragma unroll
                for (int i = 0; i < 8; i++) {
                    u64 pd = dup_f2(((const float*)&p4[i])[nn]);
                    fma_f2(acc[i][0], pd, v2.x);
                    fma_f2(acc[i][1], pd, v2.y);
                }
            }
        }

        cp_wait_all();     // next K and V landed
        __syncthreads();
    }

    // Deferred sum reduction, normalize, write merged-head layout
    const int b = bh >> 4;
    const int h = bh & 15;
#pragma unroll
    for (int i = 0; i < 8; i++) {
        float lsum = li[i];
#pragma unroll
        for (int off = 8; off > 0; off >>= 1)
            lsum += __shfl_xor_sync(0xffffffffu, lsum, off);
        float inv = 1.0f / lsum;
        int srow = mBase + ty * 8 + i;
        float2 o0 = unp_f2(acc[i][0]);
        float2 o1 = unp_f2(acc[i][1]);
        float* dst = Octx + ((size_t)(b * SEQ + srow)) * DMODEL + h * DK + tx * 4;
        *(float4*)dst = make_float4(o0.x * inv, o0.y * inv, o1.x * inv, o1.y * inv);
    }
}

// ---------------------------------------------------------------------------
// Launch
// ---------------------------------------------------------------------------
extern "C" void kernel_launch(void* const* d_in, const int* in_sizes, int n_in,
                              void* d_out, int out_size)
{
    const float* query = (const float*)d_in[0];
    const float* key   = (const float*)d_in[1];
    const float* value = (const float*)d_in[2];
    const float* Wq    = (const float*)d_in[3];
    const float* bq    = (const float*)d_in[4];
    const float* Wk    = (const float*)d_in[5];
    const float* bk    = (const float*)d_in[6];
    const float* Wv    = (const float*)d_in[7];
    const float* bv    = (const float*)d_in[8];
    const float* Wo    = (const float*)d_in[9];
    const float* bo    = (const float*)d_in[10];
    float* out = (float*)d_out;

    float *qp, *kp, *vp, *ctxp;
    cudaGetSymbolAddress((void**)&qp,   g_q);
    cudaGetSymbolAddress((void**)&kp,   g_k);
    cudaGetSymbolAddress((void**)&vp,   g_v);
    cudaGetSymbolAddress((void**)&ctxp, g_ctx);

    cudaFuncSetAttribute(flash_attn_kernel,
                         cudaFuncAttributeMaxDynamicSharedMemorySize, FLASH_SMEM);

    dim3 gBlk(256);
    dim3 gGrid(DMODEL / GBN, MROWS / GBM);   // 8 x 64

    // Projections: Q transposed + pre-scaled by 1/sqrt(DK)=0.125 (exact),
    // K transposed, V head-split.
    gemm_nt_bias<<<gGrid, gBlk>>>(query, Wq, bq, qp, DMODEL, DMODEL, 2, 0.125f);
    gemm_nt_bias<<<gGrid, gBlk>>>(key,   Wk, bk, kp, DMODEL, DMODEL, 2, 1.0f);
    gemm_nt_bias<<<gGrid, gBlk>>>(value, Wv, bv, vp, DMODEL, DMODEL, 1, 1.0f);

    // Attention
    dim3 fGrid(SEQ / FBM, BHTOT);            // 16 x 64
    flash_attn_kernel<<<fGrid, 256, FLASH_SMEM>>>(qp, kp, vp, ctxp);

    // Output projection
    gemm_nt_bias<<<gGrid, gBlk>>>(ctxp, Wo, bo, out, DMODEL, DMODEL, 0, 1.0f);
}

// round 17
// speedup vs baseline: 1.5615x; 1.5615x over previous
#include <cuda_runtime.h>
#include <cuda_bf16.h>
#include <math.h>

// Problem constants (fixed by reference: B=4, S=2048, D_MODEL=1024, H=16, DK=64)
#define BATCH    4
#define SEQ      2048
#define DMODEL   1024
#define NHEADS   16
#define DK       64
#define BHTOT    (BATCH * NHEADS)
#define MROWS    (BATCH * SEQ)          // 8192

typedef unsigned long long u64;
typedef unsigned int u32;
typedef unsigned short u16;

extern __shared__ char dynsm[];

// ---------------------------------------------------------------------------
// Packed fp32x2 helpers (flash attention kernel)
// ---------------------------------------------------------------------------
__device__ __forceinline__ u64 dup_f2(float x) {
    u64 r; asm("mov.b64 %0, {%1, %1};" : "=l"(r) : "f"(x)); return r;
}
__device__ __forceinline__ void fma_f2(u64& d, u64 a, u64 b) {
    asm("fma.rn.f32x2 %0, %1, %2, %0;" : "+l"(d) : "l"(a), "l"(b));
}
__device__ __forceinline__ void mul_f2(u64& d, u64 a, u64 b) {
    asm("mul.rn.f32x2 %0, %1, %2;" : "=l"(d) : "l"(a), "l"(b));
}
__device__ __forceinline__ float2 unp_f2(u64 v) {
    float lo, hi; asm("mov.b64 {%0, %1}, %2;" : "=f"(lo), "=f"(hi) : "l"(v));
    return make_float2(lo, hi);
}

// cp.async helpers (16B)
__device__ __forceinline__ void cp16(u32 dst, const void* src) {
    asm volatile("cp.async.cg.shared.global [%0], [%1], 16;" :: "r"(dst), "l"(src));
}
__device__ __forceinline__ void cp_commit() {
    asm volatile("cp.async.commit_group;");
}
__device__ __forceinline__ void cp_wait_all() {
    asm volatile("cp.async.wait_group 0;");
}

// Warp-MMA helpers (family-common: sm_80+, compiles for plain sm_103)
__device__ __forceinline__ void ldsm4(u32& r0, u32& r1, u32& r2, u32& r3, u32 a) {
    asm volatile("ldmatrix.sync.aligned.m8n8.x4.shared.b16 {%0,%1,%2,%3}, [%4];"
                 : "=r"(r0), "=r"(r1), "=r"(r2), "=r"(r3) : "r"(a));
}
__device__ __forceinline__ void mma16816(float* c, u32 a0, u32 a1, u32 a2, u32 a3,
                                         u32 b0, u32 b1) {
    asm volatile("mma.sync.aligned.m16n8k16.row.col.f32.bf16.bf16.f32 "
                 "{%0,%1,%2,%3}, {%4,%5,%6,%7}, {%8,%9}, {%0,%1,%2,%3};"
                 : "+f"(c[0]), "+f"(c[1]), "+f"(c[2]), "+f"(c[3])
                 : "r"(a0), "r"(a1), "r"(a2), "r"(a3), "r"(b0), "r"(b1));
}

// ---------------------------------------------------------------------------
// Scratch (static device globals — no runtime allocation)
// ---------------------------------------------------------------------------
__device__ float g_q[BHTOT * DK * SEQ];      // [bh][d][s]  (TRANSPOSED, pre-scaled)
__device__ float g_k[BHTOT * DK * SEQ];      // [bh][d][s]  (TRANSPOSED)
__device__ float g_v[BHTOT * SEQ * DK];      // [bh][s][d]
__device__ float g_ctx[MROWS * DMODEL];      // [b*S+s][h*DK+d]
__device__ u16 g_ahi[MROWS * DMODEL];        // bf16 hi/lo splits of activation
__device__ u16 g_alo[MROWS * DMODEL];
__device__ u16 g_whi[DMODEL * DMODEL];       // bf16 hi/lo splits of weight
__device__ u16 g_wlo[DMODEL * DMODEL];

// ---------------------------------------------------------------------------
// fp32 -> bf16 hi/lo split (Ootomo): x = hi + lo + O(2^-17 x)
// ---------------------------------------------------------------------------
__global__ __launch_bounds__(256) void split_bf16_kernel(
    const float* __restrict__ src, u16* __restrict__ hi, u16* __restrict__ lo, int n4)
{
    int i = blockIdx.x * blockDim.x + threadIdx.x;
    if (i >= n4) return;
    float4 v = ((const float4*)src)[i];
    __nv_bfloat16 h0 = __float2bfloat16(v.x);
    __nv_bfloat16 h1 = __float2bfloat16(v.y);
    __nv_bfloat16 h2 = __float2bfloat16(v.z);
    __nv_bfloat16 h3 = __float2bfloat16(v.w);
    __nv_bfloat16 l0 = __float2bfloat16(v.x - __bfloat162float(h0));
    __nv_bfloat16 l1 = __float2bfloat16(v.y - __bfloat162float(h1));
    __nv_bfloat16 l2 = __float2bfloat16(v.z - __bfloat162float(h2));
    __nv_bfloat16 l3 = __float2bfloat16(v.w - __bfloat162float(h3));
    ((ushort4*)hi)[i] = make_ushort4(*(u16*)&h0, *(u16*)&h1, *(u16*)&h2, *(u16*)&h3);
    ((ushort4*)lo)[i] = make_ushort4(*(u16*)&l0, *(u16*)&l1, *(u16*)&l2, *(u16*)&l3);
}

// ---------------------------------------------------------------------------
// Warp-MMA bf16-split GEMM: C[m,n] = (sum_k A[m,k]W[n,k] + bias[n]) * oscale
// D = AhiWhi + AhiWlo + AloWhi  (fp32 accumulators; ~1e-5 rel accuracy)
// CTA 128x128, 8 warps (2x4), warp tile 64x32, m16n8k16 fragments.
// K chunks of 32, smem stride 40 elems (bank-conflict-free ldmatrix, 16B rows),
// cp.async double-buffered.
// mode 0: C[m][n]   mode 1: [bh][s][d]   mode 2: [bh][d][s]
// ---------------------------------------------------------------------------
#define KC 32
#define TSTR 40
#define TILE_ELEMS (128 * TSTR)
#define MMA_SMEM (8 * TILE_ELEMS * 2)      // 81920 B

__global__ __launch_bounds__(256, 2) void mma_gemm(
    const u16* __restrict__ Ahi, const u16* __restrict__ Alo,
    const u16* __restrict__ Whi, const u16* __restrict__ Wlo,
    const float* __restrict__ bias, float* __restrict__ C,
    int mode, float oscale)
{
    const int tid = threadIdx.x, lane = tid & 31, wid = tid >> 5;
    const int wr = wid >> 2, wc = wid & 3;
    const int mBase = blockIdx.y * 128, nBase = blockIdx.x * 128;
    const u32 sbase = (u32)__cvta_generic_to_shared(dynsm);
    const int q = lane >> 3, rl = lane & 7;

    float c[4][4][4];
#pragma unroll
    for (int i = 0; i < 4; i++)
#pragma unroll
        for (int j = 0; j < 4; j++)
#pragma unroll
            for (int t = 0; t < 4; t++) c[i][j][t] = 0.0f;

    // Per-chunk async fill: 4 tiles x 128 rows x 64B = 2048 16B chunks
    auto issue = [&](int buf, int kc) {
#pragma unroll
        for (int t = 0; t < 8; t++) {
            int ci = tid + t * 256;            // 0..2047
            int tile = ci >> 9;                // 0=Ahi 1=Alo 2=Whi 3=Wlo
            int idx = ci & 511;
            int r = idx >> 2, c16 = idx & 3;
            u32 dst = sbase + (u32)(((buf * 4 + tile) * TILE_ELEMS
                                     + r * TSTR + c16 * 8) * 2);
            const u16* src;
            if (tile < 2) {
                size_t off = (size_t)(mBase + r) * DMODEL + kc * KC + c16 * 8;
                src = (tile == 0 ? Ahi : Alo) + off;
            } else {
                size_t off = (size_t)(nBase + r) * DMODEL + kc * KC + c16 * 8;
                src = (tile == 2 ? Whi : Wlo) + off;
            }
            cp16(dst, src);
        }
        cp_commit();
    };

    issue(0, 0);
    cp_wait_all();
    __syncthreads();

    for (int kc = 0; kc < DMODEL / KC; kc++) {
        int buf = kc & 1;
        if (kc + 1 < DMODEL / KC) issue(buf ^ 1, kc + 1);

        const u32 tAhi = sbase + (u32)((buf * 4 + 0) * TILE_ELEMS * 2);
        const u32 tAlo = sbase + (u32)((buf * 4 + 1) * TILE_ELEMS * 2);
        const u32 tWhi = sbase + (u32)((buf * 4 + 2) * TILE_ELEMS * 2);
        const u32 tWlo = sbase + (u32)((buf * 4 + 3) * TILE_ELEMS * 2);

#pragma unroll
        for (int ks = 0; ks < 2; ks++) {
            const int k0 = ks * 16;
            const u32 lcol = (u32)(k0 + (q >> 1) * 8);

            // B fragments: ldmatrix.x4 covers two n-tiles (16 n-rows, k16)
            u32 bhi[2][4], blo[2][4];
#pragma unroll
            for (int jj = 0; jj < 2; jj++) {
                u32 row = (u32)(wc * 32 + jj * 16 + (q & 1) * 8 + rl);
                u32 off = (row * TSTR + lcol) * 2;
                ldsm4(bhi[jj][0], bhi[jj][1], bhi[jj][2], bhi[jj][3], tWhi + off);
                ldsm4(blo[jj][0], blo[jj][1], blo[jj][2], blo[jj][3], tWlo + off);
            }

#pragma unroll
            for (int i = 0; i < 4; i++) {
                u32 row = (u32)(wr * 64 + i * 16 + (q & 1) * 8 + rl);
                u32 off = (row * TSTR + lcol) * 2;
                u32 ah0, ah1, ah2, ah3, al0, al1, al2, al3;
                ldsm4(ah0, ah1, ah2, ah3, tAhi + off);
                ldsm4(al0, al1, al2, al3, tAlo + off);
#pragma unroll
                for (int j = 0; j < 4; j++) {
                    int jj = j >> 1, sel = j & 1;
                    u32 b0h = bhi[jj][sel], b1h = bhi[jj][2 + sel];
                    u32 b0l = blo[jj][sel], b1l = blo[jj][2 + sel];
                    mma16816(c[i][j], ah0, ah1, ah2, ah3, b0h, b1h);
                    mma16816(c[i][j], ah0, ah1, ah2, ah3, b0l, b1l);
                    mma16816(c[i][j], al0, al1, al2, al3, b0h, b1h);
                }
            }
        }

        cp_wait_all();
        __syncthreads();
    }

    // Epilogue
    auto store2 = [&](int m, int n, float v0, float v1) {
        v0 = (v0 + bias[n])     * oscale;
        v1 = (v1 + bias[n + 1]) * oscale;
        if (mode == 0) {
            *(float2*)&C[(size_t)m * DMODEL + n] = make_float2(v0, v1);
        } else if (mode == 1) {
            int b = m >> 11, s = m & (SEQ - 1), h = n >> 6, d = n & (DK - 1);
            *(float2*)&C[(((size_t)(b * NHEADS + h)) * SEQ + s) * DK + d] =
                make_float2(v0, v1);
        } else {
            int b = m >> 11, s = m & (SEQ - 1), h = n >> 6, d = n & (DK - 1);
            size_t base = (((size_t)(b * NHEADS + h)) * DK + d) * SEQ + s;
            C[base]       = v0;
            C[base + SEQ] = v1;
        }
    };

#pragma unroll
    for (int i = 0; i < 4; i++) {
#pragma unroll
        for (int j = 0; j < 4; j++) {
            int row = mBase + wr * 64 + i * 16 + (lane >> 2);
            int col = nBase + wc * 32 + j * 8 + (lane & 3) * 2;
            store2(row,     col, c[i][j][0], c[i][j][1]);
            store2(row + 8, col, c[i][j][2], c[i][j][3]);
        }
    }
}

// ---------------------------------------------------------------------------
// Flash attention v3 (R12, measured best): 128-row Q tiles, 64-col KV tiles.
// Q/K arrive transposed ([bh][d][s], Q pre-scaled); straight cp.async fills;
// V ping-pong; K prefetched after its last read. 16x16 threads, 8x4 micro.
// ---------------------------------------------------------------------------
#define FBM 128
#define FBN 64
#define NTILE (SEQ / FBN)
#define FLASH_SMEM ((DK * FBM + DK * FBN + 2 * FBN * DK + FBM * FBN) * (int)sizeof(float))

__global__ __launch_bounds__(256, 2) void flash_attn_kernel(
    const float* __restrict__ Q, const float* __restrict__ K,
    const float* __restrict__ V, float* __restrict__ Octx)
{
    float* fsm = (float*)dynsm;
    float* Qst = fsm;                       // [64][128]  Qst[d*128 + m]
    float* Kst = Qst + DK * FBM;            // [64][64]   Kst[d*64 + n]
    float* Vs0 = Kst + DK * FBN;            // [64][64]   ping
    float* Vs1 = Vs0 + FBN * DK;            // [64][64]   pong
    float* Ps  = Vs1 + FBN * DK;            // [128][64]  Ps[m*64 + n]

    const int tid = threadIdx.x;
    const int tx = tid & 15;
    const int ty = tid >> 4;
    const int bh = blockIdx.y;
    const int mBase = blockIdx.x * FBM;

    const float* Qt = Q + (size_t)bh * DK * SEQ;   // [d][s]
    const float* Kt = K + (size_t)bh * DK * SEQ;   // [d][s]
    const float* Vp = V + (size_t)bh * SEQ * DK;   // [s][d]

    const u32 sQ  = (u32)__cvta_generic_to_shared(Qst);
    const u32 sK  = (u32)__cvta_generic_to_shared(Kst);
    const u32 sV0 = (u32)__cvta_generic_to_shared(Vs0);
    const u32 sV1 = (u32)__cvta_generic_to_shared(Vs1);

#pragma unroll
    for (int k = 0; k < 8; k++) {              // Q: 2048 16B chunks
        int c = tid + k * 256;
        int d = c >> 5, m4 = (c & 31) * 4;
        cp16(sQ + (u32)(d * FBM + m4) * 4, Qt + (size_t)d * SEQ + mBase + m4);
    }
#pragma unroll
    for (int k = 0; k < 4; k++) {              // K: 1024 16B chunks
        int c = tid + k * 256;
        int d = c >> 4, n4 = (c & 15) * 4;
        cp16(sK + (u32)(d * FBN + n4) * 4, Kt + (size_t)d * SEQ + n4);
    }
#pragma unroll
    for (int k = 0; k < 4; k++) {              // V: 1024 16B chunks
        int c = tid + k * 256;
        cp16(sV0 + (u32)c * 16, Vp + c * 4);
    }
    cp_commit();
    cp_wait_all();
    __syncthreads();

    u64 acc[8][2];
    float mi[8], li[8];
#pragma unroll
    for (int i = 0; i < 8; i++) {
        mi[i] = -1e30f; li[i] = 0.0f;
        acc[i][0] = 0ull; acc[i][1] = 0ull;
    }

    for (int it = 0; it < NTILE; it++) {
        const int n0 = it * FBN;
        const float* Vcur = (it & 1) ? Vs1 : Vs0;
        const u32 sVnxt   = (it & 1) ? sV0 : sV1;

        if (it + 1 < NTILE) {
#pragma unroll
            for (int k = 0; k < 4; k++) {
                int c = tid + k * 256;
                cp16(sVnxt + (u32)c * 16, Vp + (size_t)(n0 + FBN) * DK + c * 4);
            }
            cp_commit();
        }

        u64 sp[8][2];
#pragma unroll
        for (int i = 0; i < 8; i++) { sp[i][0] = 0ull; sp[i][1] = 0ull; }

#pragma unroll 4
        for (int d = 0; d < DK; d++) {
            ulonglong2 b2 = *(const ulonglong2*)&Kst[d * FBN + tx * 4];
            float4 a0 = *(const float4*)&Qst[d * FBM + ty * 8];
            float4 a1 = *(const float4*)&Qst[d * FBM + ty * 8 + 4];
            float av[8] = {a0.x, a0.y, a0.z, a0.w, a1.x, a1.y, a1.z, a1.w};
#pragma unroll
            for (int i = 0; i < 8; i++) {
                u64 ad = dup_f2(av[i]);
                fma_f2(sp[i][0], ad, b2.x);
                fma_f2(sp[i][1], ad, b2.y);
            }
        }

        float s[8][4];
#pragma unroll
        for (int i = 0; i < 8; i++) {
            float2 p0 = unp_f2(sp[i][0]);
            float2 p1 = unp_f2(sp[i][1]);
            s[i][0] = p0.x; s[i][1] = p0.y; s[i][2] = p1.x; s[i][3] = p1.y;
        }

#pragma unroll
        for (int i = 0; i < 8; i++) {
            float rm = fmaxf(fmaxf(s[i][0], s[i][1]), fmaxf(s[i][2], s[i][3]));
#pragma unroll
            for (int off = 8; off > 0; off >>= 1)
                rm = fmaxf(rm, __shfl_xor_sync(0xffffffffu, rm, off));
            float mnew = fmaxf(mi[i], rm);
            float alpha = __expf(mi[i] - mnew);
            float rs = 0.0f;
#pragma unroll
            for (int j = 0; j < 4; j++) {
                s[i][j] = __expf(s[i][j] - mnew);
                rs += s[i][j];
            }
            li[i] = li[i] * alpha + rs;
            mi[i] = mnew;
            u64 al = dup_f2(alpha);
            mul_f2(acc[i][0], acc[i][0], al);
            mul_f2(acc[i][1], acc[i][1], al);
        }

        __syncthreads();

        if (it + 1 < NTILE) {
#pragma unroll
            for (int k = 0; k < 4; k++) {
                int c = tid + k * 256;
                int d = c >> 4, n4 = (c & 15) * 4;
                cp16(sK + (u32)(d * FBN + n4) * 4,
                     Kt + (size_t)d * SEQ + (n0 + FBN) + n4);
            }
            cp_commit();
        }

#pragma unroll
        for (int i = 0; i < 8; i++)
            *(float4*)&Ps[(ty * 8 + i) * FBN + tx * 4] =
                make_float4(s[i][0], s[i][1], s[i][2], s[i][3]);
        __syncthreads();

#pragma unroll 2
        for (int n = 0; n < FBN; n += 4) {
            float4 p4[8];
#pragma unroll
            for (int i = 0; i < 8; i++)
                p4[i] = *(const float4*)&Ps[(ty * 8 + i) * FBN + n];
#pragma unroll
            for (int nn = 0; nn < 4; nn++) {
                ulonglong2 v2 = *(const ulonglong2*)&Vcur[(n + nn) * DK + tx * 4];
#pragma unroll
                for (int i = 0; i < 8; i++) {
                    u64 pd = dup_f2(((const float*)&p4[i])[nn]);
                    fma_f2(acc[i][0], pd, v2.x);
                    fma_f2(acc[i][1], pd, v2.y);
                }
            }
        }

        cp_wait_all();
        __syncthreads();
    }

    const int b = bh >> 4;
    const int h = bh & 15;
#pragma unroll
    for (int i = 0; i < 8; i++) {
        float lsum = li[i];
#pragma unroll
        for (int off = 8; off > 0; off >>= 1)
            lsum += __shfl_xor_sync(0xffffffffu, lsum, off);
        float inv = 1.0f / lsum;
        int srow = mBase + ty * 8 + i;
        float2 o0 = unp_f2(acc[i][0]);
        float2 o1 = unp_f2(acc[i][1]);
        float* dst = Octx + ((size_t)(b * SEQ + srow)) * DMODEL + h * DK + tx * 4;
        *(float4*)dst = make_float4(o0.x * inv, o0.y * inv, o1.x * inv, o1.y * inv);
    }
}

// ---------------------------------------------------------------------------
// Launch
// ---------------------------------------------------------------------------
extern "C" void kernel_launch(void* const* d_in, const int* in_sizes, int n_in,
                              void* d_out, int out_size)
{
    const float* query = (const float*)d_in[0];
    const float* key   = (const float*)d_in[1];
    const float* value = (const float*)d_in[2];
    const float* Wq    = (const float*)d_in[3];
    const float* bq    = (const float*)d_in[4];
    const float* Wk    = (const float*)d_in[5];
    const float* bk    = (const float*)d_in[6];
    const float* Wv    = (const float*)d_in[7];
    const float* bv    = (const float*)d_in[8];
    const float* Wo    = (const float*)d_in[9];
    const float* bo    = (const float*)d_in[10];
    float* out = (float*)d_out;

    float *qp, *kp, *vp, *ctxp;
    u16 *ahi, *alo, *whi, *wlo;
    cudaGetSymbolAddress((void**)&qp,   g_q);
    cudaGetSymbolAddress((void**)&kp,   g_k);
    cudaGetSymbolAddress((void**)&vp,   g_v);
    cudaGetSymbolAddress((void**)&ctxp, g_ctx);
    cudaGetSymbolAddress((void**)&ahi,  g_ahi);
    cudaGetSymbolAddress((void**)&alo,  g_alo);
    cudaGetSymbolAddress((void**)&whi,  g_whi);
    cudaGetSymbolAddress((void**)&wlo,  g_wlo);

    cudaFuncSetAttribute(flash_attn_kernel,
                         cudaFuncAttributeMaxDynamicSharedMemorySize, FLASH_SMEM);
    cudaFuncSetAttribute(mma_gemm,
                         cudaFuncAttributeMaxDynamicSharedMemorySize, MMA_SMEM);

    const int n4A = MROWS * DMODEL / 4;
    const int n4W = DMODEL * DMODEL / 4;
    dim3 gGrid(DMODEL / 128, MROWS / 128);   // 8 x 64

    // Q projection: transposed [bh][d][s], pre-scaled by 1/sqrt(DK)=0.125
    split_bf16_kernel<<<(n4A + 255) / 256, 256>>>(query, ahi, alo, n4A);
    split_bf16_kernel<<<(n4W + 255) / 256, 256>>>(Wq, whi, wlo, n4W);
    mma_gemm<<<gGrid, 256, MMA_SMEM>>>(ahi, alo, whi, wlo, bq, qp, 2, 0.125f);

    // K projection: transposed [bh][d][s]
    split_bf16_kernel<<<(n4A + 255) / 256, 256>>>(key, ahi, alo, n4A);
    split_bf16_kernel<<<(n4W + 255) / 256, 256>>>(Wk, whi, wlo, n4W);
    mma_gemm<<<gGrid, 256, MMA_SMEM>>>(ahi, alo, whi, wlo, bk, kp, 2, 1.0f);

    // V projection: head-split [bh][s][d]
    split_bf16_kernel<<<(n4A + 255) / 256, 256>>>(value, ahi, alo, n4A);
    split_bf16_kernel<<<(n4W + 255) / 256, 256>>>(Wv, whi, wlo, n4W);
    mma_gemm<<<gGrid, 256, MMA_SMEM>>>(ahi, alo, whi, wlo, bv, vp, 1, 1.0f);

    // Attention
    dim3 fGrid(SEQ / FBM, BHTOT);            // 16 x 64
    flash_attn_kernel<<<fGrid, 256, FLASH_SMEM>>>(qp, kp, vp, ctxp);

    // Output projection
    split_bf16_kernel<<<(n4A + 255) / 256, 256>>>(ctxp, ahi, alo, n4A);
    split_bf16_kernel<<<(n4W + 255) / 256, 256>>>(Wo, whi, wlo, n4W);
    mma_gemm<<<gGrid, 256, MMA_SMEM>>>(ahi, alo, whi, wlo, bo, out, 0, 1.0f);
}